// round 14
// baseline (speedup 1.0000x reference)
#include <cuda_runtime.h>

// CRF forward loss: B=1024, T=512, K=32.
// inputs: emissions f32 [B,T,K], tags i32 [B,T], mask int32 [B,T], trans f32 [K,K]
// output: scalar f32 loss = mean_b( log_z - em_score - tr_score )
//
// R12 (= R11 resubmit after infra failure, + WAR-race fix on the p buffer):
//   2 batches per warp (shared E), packed f32x2 dot, log2-domain chain.
//   lane j owns state j for BOTH chains. E2[i] = (exp(tr[i][j]), exp(tr[i][j])).
//   step: pA=ex2(aA), pB=ex2(aB); STS.64 (pA,pB); syncwarp;
//         16x LDS.128 -> 32x fma.rn.f32x2 -> (sA,sB); syncwarp (WAR);
//         v = lg2(s) + em*log2e (premult in ring); a = mask ? v : a.
//   Renorm (exact uniform shift by lane0) once per 4 steps per chain.
//   Path scores lane-parallel per 32-step chunk + warp reduction at the end
//   (R9/R10 forgot the reduction -> rel_err 4.3e-4; passed by luck).
//   Final mean fused via last-block reduction (atomicInc wrap counter).

#define FULLM 0xffffffffu
typedef unsigned long long ull;

constexpr int Bc  = 1024;
constexpr int Tc  = 512;
constexpr int Kc  = 32;
constexpr int WPB = 4;                      // warps per block
constexpr int NBLK = Bc / (WPB * 2);        // 128 blocks, 2 batches/warp

__device__ float    g_partial[Bc];
__device__ unsigned g_ctr = 0;              // wraps to 0 each launch -> replay-safe

__device__ __forceinline__ ull pk2(float lo, float hi) {
    ull r; asm("mov.b64 %0, {%1,%2};" : "=l"(r) : "f"(lo), "f"(hi)); return r;
}
__device__ __forceinline__ void upk2(float& lo, float& hi, ull v) {
    asm("mov.b64 {%0,%1}, %2;" : "=f"(lo), "=f"(hi) : "l"(v));
}
__device__ __forceinline__ ull ffma2(ull a, ull b, ull c) {
    ull d; asm("fma.rn.f32x2 %0, %1, %2, %3;" : "=l"(d) : "l"(a), "l"(b), "l"(c)); return d;
}
__device__ __forceinline__ ull fmul2(ull a, ull b) {
    ull d; asm("mul.rn.f32x2 %0, %1, %2;" : "=l"(d) : "l"(a), "l"(b)); return d;
}
__device__ __forceinline__ ull fadd2(ull a, ull b) {
    ull d; asm("add.rn.f32x2 %0, %1, %2;" : "=l"(d) : "l"(a), "l"(b)); return d;
}
__device__ __forceinline__ float ex2f_(float x) {
    float r; asm("ex2.approx.f32 %0, %1;" : "=f"(r) : "f"(x)); return r;
}
__device__ __forceinline__ float lg2f_(float x) {
    float r; asm("lg2.approx.f32 %0, %1;" : "=f"(r) : "f"(x)); return r;
}

__global__ void __launch_bounds__(128, 1)
crf_forward(const float* __restrict__ em,
            const int* __restrict__ tags,
            const int* __restrict__ mask,
            const float* __restrict__ trans,
            float* __restrict__ out)
{
    __shared__ float tr_s[Kc * Kc];
    __shared__ __align__(16) ull pb[WPB][Kc];   // per-warp packed (pA,pB)
    __shared__ float red[WPB];
    __shared__ int   sdone;

    const int lane = threadIdx.x & 31;
    const int wid  = threadIdx.x >> 5;

    for (int i = threadIdx.x; i < Kc * Kc; i += 128)
        tr_s[i] = trans[i];
    __syncthreads();

    const float L2E = 1.4426950408889634f;   // log2(e)
    const float LN2 = 0.6931471805599453f;

    // lane j holds column j of E = exp(transitions), duplicated into pairs
    ull E2[Kc];
#pragma unroll
    for (int i = 0; i < Kc; i++) {
        float e = __expf(tr_s[i * Kc + lane]);
        E2[i] = pk2(e, e);
    }

    const int b0 = (blockIdx.x * WPB + wid) * 2;
    const int b1 = b0 + 1;

    const float* emA = em   + (size_t)b0 * Tc * Kc;
    const float* emB = em   + (size_t)b1 * Tc * Kc;
    const int*   tgA = tags + (size_t)b0 * Tc;
    const int*   tgB = tags + (size_t)b1 * Tc;
    const int*   mAp = mask + (size_t)b0 * Tc;
    const int*   mBp = mask + (size_t)b1 * Tc;

    // ---- init: alpha0 = em[0]  (log2 domain, lane0-normalized) ----
    float e0A = emA[lane];
    float e0B = emB[lane];
    float r0A = __shfl_sync(FULLM, e0A, 0);
    float r0B = __shfl_sync(FULLM, e0B, 0);
    float aA = (e0A - r0A) * L2E, cA = r0A * L2E;
    float aB = (e0B - r0B) * L2E, cB = r0B * L2E;

    // prefetch ring: em rows t..t+3, premultiplied by log2(e)
    float nA0 = emA[0 * Kc + lane] * L2E;
    float nA1 = emA[1 * Kc + lane] * L2E;
    float nA2 = emA[2 * Kc + lane] * L2E;
    float nA3 = emA[3 * Kc + lane] * L2E;
    float nB0 = emB[0 * Kc + lane] * L2E;
    float nB1 = emB[1 * Kc + lane] * L2E;
    float nB2 = emB[2 * Kc + lane] * L2E;
    float nB3 = emB[3 * Kc + lane] * L2E;

    float esA = 0.f, tsA = 0.f, esB = 0.f, tsB = 0.f;
    int cryA = 0, cryB = 0;

    for (int ch = 0; ch < Tc / 32; ch++) {
        // ---- lane-parallel path scores for this 32-step chunk ----
        const int t_l = ch * 32 + lane;
        int ta = tgA[t_l], tb_ = tgB[t_l];
        int ma = mAp[t_l], mb = mBp[t_l];
        unsigned mbA = __ballot_sync(FULLM, ma != 0);
        unsigned mbB = __ballot_sync(FULLM, mb != 0);
        int tpA = __shfl_up_sync(FULLM, ta, 1);
        int tpB = __shfl_up_sync(FULLM, tb_, 1);
        if (lane == 0) { tpA = cryA; tpB = cryB; }
        cryA = __shfl_sync(FULLM, ta, 31);
        cryB = __shfl_sync(FULLM, tb_, 31);
        float etA = emA[(size_t)t_l * Kc + ta];
        float etB = emB[(size_t)t_l * Kc + tb_];
        if (ma) { esA += etA; if (t_l > 0) tsA += tr_s[tpA * Kc + ta]; }
        if (mb) { esB += etB; if (t_l > 0) tsB += tr_s[tpB * Kc + tb_]; }

        for (int jj = 0; jj < 32; jj += 4) {
            const int tb0 = ch * 32 + jj;

            // exact uniform-shift renorm, once per 4 steps (mask-safe)
            float sh;
            sh = __shfl_sync(FULLM, aA, 0); aA -= sh; cA += sh;
            sh = __shfl_sync(FULLM, aB, 0); aB -= sh; cB += sh;

            float qA[4] = {nA0, nA1, nA2, nA3};
            float qB[4] = {nB0, nB1, nB2, nB3};
            int t4 = min(tb0 + 4, Tc - 1);
            int t5 = min(tb0 + 5, Tc - 1);
            int t6 = min(tb0 + 6, Tc - 1);
            int t7 = min(tb0 + 7, Tc - 1);
            nA0 = emA[t4 * Kc + lane] * L2E;
            nA1 = emA[t5 * Kc + lane] * L2E;
            nA2 = emA[t6 * Kc + lane] * L2E;
            nA3 = emA[t7 * Kc + lane] * L2E;
            nB0 = emB[t4 * Kc + lane] * L2E;
            nB1 = emB[t5 * Kc + lane] * L2E;
            nB2 = emB[t6 * Kc + lane] * L2E;
            nB3 = emB[t7 * Kc + lane] * L2E;

#pragma unroll
            for (int q = 0; q < 4; q++) {
                const int t = tb0 + q;
                if (t != 0) {
                    float pA = ex2f_(aA);
                    float pB = ex2f_(aB);
                    pb[wid][lane] = pk2(pA, pB);      // one STS.64
                    __syncwarp();                     // RAW: stores -> loads
                    const ulonglong2* pv =
                        reinterpret_cast<const ulonglong2*>(pb[wid]);

                    ulonglong2 x0 = pv[0], x1 = pv[1];
                    ull a0 = fmul2(x0.x, E2[0]);
                    ull a1 = fmul2(x0.y, E2[1]);
                    ull a2 = fmul2(x1.x, E2[2]);
                    ull a3 = fmul2(x1.y, E2[3]);
#pragma unroll
                    for (int i = 2; i < 16; i += 2) {
                        ulonglong2 xa = pv[i], xb = pv[i + 1];
                        a0 = ffma2(xa.x, E2[2 * i + 0], a0);
                        a1 = ffma2(xa.y, E2[2 * i + 1], a1);
                        a2 = ffma2(xb.x, E2[2 * i + 2], a2);
                        a3 = ffma2(xb.y, E2[2 * i + 3], a3);
                    }
                    __syncwarp();                     // WAR: loads -> next store
                    ull sp = fadd2(fadd2(a0, a1), fadd2(a2, a3));
                    float sA, sB;
                    upk2(sA, sB, sp);

                    float vA = lg2f_(sA) + qA[q];
                    float vB = lg2f_(sB) + qB[q];
                    aA = ((mbA >> (jj + q)) & 1u) ? vA : aA;
                    aB = ((mbB >> (jj + q)) & 1u) ? vB : aB;
                }
            }
        }
    }

    // ---- final logsumexp (log2 domain) per chain ----
    float mxA = aA, mxB = aB;
#pragma unroll
    for (int o = 16; o; o >>= 1) {
        mxA = fmaxf(mxA, __shfl_xor_sync(FULLM, mxA, o));
        mxB = fmaxf(mxB, __shfl_xor_sync(FULLM, mxB, o));
    }
    float xA = ex2f_(aA - mxA);
    float xB = ex2f_(aB - mxB);
    // fold the score reduction into the same butterflies
    float scA = esA + tsA;
    float scB = esB + tsB;
#pragma unroll
    for (int o = 16; o; o >>= 1) {
        xA  += __shfl_xor_sync(FULLM, xA, o);
        xB  += __shfl_xor_sync(FULLM, xB, o);
        scA += __shfl_xor_sync(FULLM, scA, o);
        scB += __shfl_xor_sync(FULLM, scB, o);
    }
    float logzA = (cA + mxA + lg2f_(xA)) * LN2;
    float logzB = (cB + mxB + lg2f_(xB)) * LN2;

    if (lane == 0) {
        __stcg(&g_partial[b0], logzA - scA);
        __stcg(&g_partial[b1], logzB - scB);
    }

    // ---- fused mean: last block to arrive reduces all partials ----
    __syncthreads();
    if (threadIdx.x == 0) {
        __threadfence();
        unsigned r = atomicInc(&g_ctr, (unsigned)gridDim.x - 1);
        sdone = (r == gridDim.x - 1) ? 1 : 0;
    }
    __syncthreads();
    if (sdone) {
        float s = 0.f;
        for (int i = threadIdx.x; i < Bc; i += 128)
            s += __ldcg(&g_partial[i]);
#pragma unroll
        for (int o = 16; o; o >>= 1)
            s += __shfl_xor_sync(FULLM, s, o);
        if (lane == 0) red[wid] = s;
        __syncthreads();
        if (threadIdx.x < 32) {
            float v = (threadIdx.x < WPB) ? red[threadIdx.x] : 0.f;
#pragma unroll
            for (int o = 2; o; o >>= 1)
                v += __shfl_xor_sync(FULLM, v, o);
            if (threadIdx.x == 0)
                out[0] = v * (1.0f / (float)Bc);
        }
    }
}

extern "C" void kernel_launch(void* const* d_in, const int* in_sizes, int n_in,
                              void* d_out, int out_size)
{
    const float* em    = (const float*)d_in[0];
    const int*   tags  = (const int*)d_in[1];
    const int*   mask  = (const int*)d_in[2];
    const float* trans = (const float*)d_in[3];
    float*       out   = (float*)d_out;

    crf_forward<<<NBLK, 128>>>(em, tags, mask, trans, out);
}

// round 15
// speedup vs baseline: 1.3354x; 1.3354x over previous
#include <cuda_runtime.h>

// CRF forward loss: B=1024, T=512, K=32.
// inputs: emissions f32 [B,T,K], tags i32 [B,T], mask int32 [B,T], trans f32 [K,K]
// output: scalar f32 loss = mean_b( log_z - em_score - tr_score )
//
// R15: LINEAR-SPACE chain — zero transcendentals in the recurrence.
//   lane j owns state j; E[i] = exp(trans[i][j]) in regs (column j).
//   p_j = 2^(alpha_j - off). step: sync; 8x LDS.128 (prev p vector);
//   s_j = sum_i p_i E[i][j] (32 FFMA, 4 accs); pn = s * r_t  where
//   r_t = 2^(em*log2e) from the prefetch ring (MUFU off-chain);
//   p = mask ? pn : p; STS p.  1 syncwarp/step via double buffer.
//   Renorm every 4 steps: rb = rcp(p0) with p0 = x0.x from the dot's own
//   LDS (free); applied uniformly AFTER the select of the block's first
//   step (unit-consistent); cacc -= lg2(rb) (exact vs actual multiplier).
//   Tags/mask prefetched 2 chunks ahead, emtag gather 1 chunk ahead.
//   Scores warp-reduced (R12 fix). Fused mean via atomicInc-wrap.

#define FULLM 0xffffffffu

constexpr int Bc  = 1024;
constexpr int Tc  = 512;
constexpr int Kc  = 32;
constexpr int WPB = 8;                       // warps per block
constexpr int NBLK = Bc / WPB;               // 128 blocks, 1 batch/warp

__device__ float    g_partial[Bc];
__device__ unsigned g_ctr = 0;               // wraps to 0 each launch -> replay-safe

__device__ __forceinline__ float ex2f_(float x) {
    float r; asm("ex2.approx.f32 %0, %1;" : "=f"(r) : "f"(x)); return r;
}
__device__ __forceinline__ float lg2f_(float x) {
    float r; asm("lg2.approx.f32 %0, %1;" : "=f"(r) : "f"(x)); return r;
}
__device__ __forceinline__ float rcpf_(float x) {
    float r; asm("rcp.approx.f32 %0, %1;" : "=f"(r) : "f"(x)); return r;
}

__global__ void __launch_bounds__(256, 1)
crf_forward(const float* __restrict__ em,
            const int* __restrict__ tags,
            const int* __restrict__ mask,
            const float* __restrict__ trans,
            float* __restrict__ out)
{
    __shared__ float tr_s[Kc * Kc];
    __shared__ __align__(16) float pbuf[WPB][2][Kc];  // double-buffered p
    __shared__ float red[WPB];
    __shared__ int   sdone;

    const int lane = threadIdx.x & 31;
    const int wid  = threadIdx.x >> 5;

    for (int i = threadIdx.x; i < Kc * Kc; i += 256)
        tr_s[i] = trans[i];
    __syncthreads();

    const float L2E = 1.4426950408889634f;   // log2(e)
    const float LN2 = 0.6931471805599453f;

    // lane j holds column j of E = exp(transitions)
    float E[Kc];
#pragma unroll
    for (int i = 0; i < Kc; i++)
        E[i] = __expf(tr_s[i * Kc + lane]);

    const int b = blockIdx.x * WPB + wid;
    const float* emB = em   + (size_t)b * Tc * Kc;
    const int*   tgB = tags + (size_t)b * Tc;
    const int*   mB  = mask + (size_t)b * Tc;

    // ---- init: alpha0 = em[0]; p = 2^((em0-em0[0])*L2E); cacc(log2) ----
    float em0  = emB[lane];
    float r00  = __shfl_sync(FULLM, em0, 0);
    float cacc = r00 * L2E;
    float p    = ex2f_((em0 - r00) * L2E);    // p[0] == 1
    pbuf[wid][0][lane] = p;                    // seed buffer for t=1
    float p0seen = 1.0f;                       // tracked p[0] (pre-scale units)

    // prefetch ring: r_t = 2^(em*L2E) for rows t..t+3
    float nx0 = ex2f_(emB[0 * Kc + lane] * L2E);
    float nx1 = ex2f_(emB[1 * Kc + lane] * L2E);
    float nx2 = ex2f_(emB[2 * Kc + lane] * L2E);
    float nx3 = ex2f_(emB[3 * Kc + lane] * L2E);

    // chunk score pipeline: current chunk (c) + next chunk (n) prefetched
    int   tg_c = tgB[lane];
    int   mk_c = mB[lane];
    float et_c = emB[(size_t)lane * Kc + tg_c];   // gather for chunk 0
    int   tg_n = tgB[32 + lane];
    int   mk_n = mB[32 + lane];

    float escore = 0.f, tscore = 0.f;
    int   cry = 0;

    for (int ch = 0; ch < Tc / 32; ch++) {
        // ---- consume chunk ch's prefetched tag/mask/emtag ----
        unsigned mbits = __ballot_sync(FULLM, mk_c != 0);
        int tp = __shfl_up_sync(FULLM, tg_c, 1);
        if (lane == 0) tp = cry;
        cry = __shfl_sync(FULLM, tg_c, 31);
        const int t_l = ch * 32 + lane;
        if (mk_c) {
            escore += et_c;
            if (t_l > 0) tscore += tr_s[tp * Kc + tg_c];
        }
        // ---- prefetch: emtag gather for ch+1, tags/mask for ch+2 ----
        int chn  = min(ch + 1, Tc / 32 - 1);
        int chnn = min(ch + 2, Tc / 32 - 1);
        float et_n = emB[(size_t)(chn * 32 + lane) * Kc + tg_n];
        int tg_nn = tgB[chnn * 32 + lane];
        int mk_nn = mB[chnn * 32 + lane];

        for (int jj = 0; jj < 32; jj += 4) {
            const int tb = ch * 32 + jj;

            // renorm factor from p[0] (1-step-stale, all lanes agree)
            float rb = rcpf_(p0seen);
            float lb = lg2f_(rb);

            float rq[4] = {nx0, nx1, nx2, nx3};
            int t4 = min(tb + 4, Tc - 1);
            int t5 = min(tb + 5, Tc - 1);
            int t6 = min(tb + 6, Tc - 1);
            int t7 = min(tb + 7, Tc - 1);
            nx0 = ex2f_(emB[t4 * Kc + lane] * L2E);
            nx1 = ex2f_(emB[t5 * Kc + lane] * L2E);
            nx2 = ex2f_(emB[t6 * Kc + lane] * L2E);
            nx3 = ex2f_(emB[t7 * Kc + lane] * L2E);

#pragma unroll
            for (int q = 0; q < 4; q++) {
                const int t = tb + q;
                __syncwarp();                       // stores(t-1) -> loads(t)
                if (t != 0) {
                    const float4* pv = reinterpret_cast<const float4*>(
                        pbuf[wid][(t + 1) & 1]);    // buffer written at t-1
                    float4 x0 = pv[0], x1 = pv[1], x2 = pv[2], x3 = pv[3];
                    float4 x4 = pv[4], x5 = pv[5], x6 = pv[6], x7 = pv[7];

                    float s0 = x0.x * E[0];
                    float s1 = x0.y * E[1];
                    float s2 = x0.z * E[2];
                    float s3 = x0.w * E[3];
                    s0 = fmaf(x1.x, E[4],  s0); s1 = fmaf(x1.y, E[5],  s1);
                    s2 = fmaf(x1.z, E[6],  s2); s3 = fmaf(x1.w, E[7],  s3);
                    s0 = fmaf(x2.x, E[8],  s0); s1 = fmaf(x2.y, E[9],  s1);
                    s2 = fmaf(x2.z, E[10], s2); s3 = fmaf(x2.w, E[11], s3);
                    s0 = fmaf(x3.x, E[12], s0); s1 = fmaf(x3.y, E[13], s1);
                    s2 = fmaf(x3.z, E[14], s2); s3 = fmaf(x3.w, E[15], s3);
                    s0 = fmaf(x4.x, E[16], s0); s1 = fmaf(x4.y, E[17], s1);
                    s2 = fmaf(x4.z, E[18], s2); s3 = fmaf(x4.w, E[19], s3);
                    s0 = fmaf(x5.x, E[20], s0); s1 = fmaf(x5.y, E[21], s1);
                    s2 = fmaf(x5.z, E[22], s2); s3 = fmaf(x5.w, E[23], s3);
                    s0 = fmaf(x6.x, E[24], s0); s1 = fmaf(x6.y, E[25], s1);
                    s2 = fmaf(x6.z, E[26], s2); s3 = fmaf(x6.w, E[27], s3);
                    s0 = fmaf(x7.x, E[28], s0); s1 = fmaf(x7.y, E[29], s1);
                    s2 = fmaf(x7.z, E[30], s2); s3 = fmaf(x7.w, E[31], s3);

                    float s  = (s0 + s1) + (s2 + s3);
                    float pn = s * rq[q];
                    bool  m  = (mbits >> (jj + q)) & 1u;
                    p = m ? pn : p;
                    if (q == 0) {                   // uniform renorm, post-sel
                        p    *= rb;                 // pre-scale units -> scaled
                        cacc -= lb;
                    }
                    p0seen = (q == 0) ? x0.x * rb : x0.x;  // track p[0] in
                }                                          // current units
                pbuf[wid][t & 1][lane] = p;          // store p(t)
            }
        }

        // rotate chunk pipeline
        tg_c = tg_n; mk_c = mk_n; et_c = et_n;
        tg_n = tg_nn; mk_n = mk_nn;
    }

    // ---- final: logz = (cacc + lg2(sum_j p_j)) * ln2 ----
    float ps = p;
    float sc = escore + tscore;
#pragma unroll
    for (int o = 16; o; o >>= 1) {
        ps += __shfl_xor_sync(FULLM, ps, o);
        sc += __shfl_xor_sync(FULLM, sc, o);
    }
    float logz = (cacc + lg2f_(ps)) * LN2;

    if (lane == 0)
        __stcg(&g_partial[b], logz - sc);

    // ---- fused mean: last block to arrive reduces all partials ----
    __syncthreads();
    if (threadIdx.x == 0) {
        __threadfence();
        unsigned r = atomicInc(&g_ctr, (unsigned)gridDim.x - 1);
        sdone = (r == gridDim.x - 1) ? 1 : 0;
    }
    __syncthreads();
    if (sdone) {
        float s = 0.f;
        for (int i = threadIdx.x; i < Bc; i += 256)
            s += __ldcg(&g_partial[i]);
#pragma unroll
        for (int o = 16; o; o >>= 1)
            s += __shfl_xor_sync(FULLM, s, o);
        if (lane == 0) red[wid] = s;
        __syncthreads();
        if (threadIdx.x < 32) {
            float v = (threadIdx.x < WPB) ? red[threadIdx.x] : 0.f;
#pragma unroll
            for (int o = 4; o; o >>= 1)
                v += __shfl_xor_sync(FULLM, v, o);
            if (threadIdx.x == 0)
                out[0] = v * (1.0f / (float)Bc);
        }
    }
}

extern "C" void kernel_launch(void* const* d_in, const int* in_sizes, int n_in,
                              void* d_out, int out_size)
{
    const float* em    = (const float*)d_in[0];
    const int*   tags  = (const int*)d_in[1];
    const int*   mask  = (const int*)d_in[2];
    const float* trans = (const float*)d_in[3];
    float*       out   = (float*)d_out;

    crf_forward<<<NBLK, 256>>>(em, tags, mask, trans, out);
}